// round 5
// baseline (speedup 1.0000x reference)
#include <cuda_runtime.h>
#include <mma.h>

using namespace nvcuda;

namespace {

constexpr int T_SEQ = 128;   // sequence length
constexpr int C_DIM = 128;   // embed dim
constexpr int H_NUM = 4;     // heads
constexpr int D_HEAD = 32;   // head dim
constexpr int LDM = 128;     // leading dim of main smem buffers (floats)
constexpr int LDS_S = 132;   // leading dim of score buffer (pad: conflict-free softmax)
constexpr int NTHREADS = 256;
constexpr int CHUNK_FLOATS = 16 * 128;   // one staged weight chunk

// smem (floats): bufX(128x128) | bufQ(128x128) | bufK(128x128) | bufS(64x132)
constexpr int SMEM_FLOATS = 3 * T_SEQ * LDM + 64 * LDS_S;
constexpr int SMEM_BYTES = SMEM_FLOATS * (int)sizeof(float);

using FragA  = wmma::fragment<wmma::matrix_a, 16, 16, 8, wmma::precision::tf32, wmma::row_major>;
using FragBR = wmma::fragment<wmma::matrix_b, 16, 16, 8, wmma::precision::tf32, wmma::row_major>;
using FragBC = wmma::fragment<wmma::matrix_b, 16, 16, 8, wmma::precision::tf32, wmma::col_major>;
using FragC  = wmma::fragment<wmma::accumulator, 16, 16, 8, float>;

__device__ __forceinline__ float to_tf32(float v) { return wmma::__float_to_tf32(v); }

// C[128,128] = A(bufX)[128,128] @ W'[128,128], W'[c][h*32+d] = W[h][c][d].
// Weight k-chunks (16 x 128) double-buffered through bufW (2 x 2048 floats),
// tf32-converted. Each warp owns 16 rows x 128 cols (8 accumulator tiles) and
// reads ONLY its own 16 rows of bufX, so dst == bufX (V overwrite) is safe.
__device__ void proj_gemm(const float* __restrict__ W, float* __restrict__ dst,
                          const float* __restrict__ bufX, float* __restrict__ bufW,
                          int warp, int tid)
{
    FragC acc[8];
#pragma unroll
    for (int nt = 0; nt < 8; nt++) wmma::fill_fragment(acc[nt], 0.0f);

    const int cc    = tid >> 4;          // chunk row 0..15
    const int n0    = (tid & 15) * 8;    // output col 0..120 step 8 (stays inside a head)
    const int head  = n0 >> 5;
    const int inner = n0 & 31;
    const float* srcBase = W + head * (C_DIM * D_HEAD) + cc * D_HEAD + inner;

    auto stage = [&](int kc, float* dbuf) {
        const float* src = srcBase + kc * 16 * D_HEAD;
        float4 u0 = *reinterpret_cast<const float4*>(src);
        float4 u1 = *reinterpret_cast<const float4*>(src + 4);
        float* dch = dbuf + cc * 128 + n0;
        dch[0] = to_tf32(u0.x); dch[1] = to_tf32(u0.y); dch[2] = to_tf32(u0.z); dch[3] = to_tf32(u0.w);
        dch[4] = to_tf32(u1.x); dch[5] = to_tf32(u1.y); dch[6] = to_tf32(u1.z); dch[7] = to_tf32(u1.w);
    };

    stage(0, bufW);
    __syncthreads();   // chunk 0 staged; also orders any preceding bufX writes vs. MMA reads

#pragma unroll 1
    for (int kc = 0; kc < 8; kc++) {
        float* cur = bufW + (kc & 1) * CHUNK_FLOATS;
        float* nxt = bufW + ((kc & 1) ^ 1) * CHUNK_FLOATS;
        if (kc < 7) stage(kc + 1, nxt);   // overlap gmem load with MMA below
#pragma unroll
        for (int ks = 0; ks < 2; ks++) {
            FragA a;
            wmma::load_matrix_sync(a, bufX + (warp * 16) * LDM + kc * 16 + ks * 8, LDM);
#pragma unroll
            for (int nt = 0; nt < 8; nt++) {
                FragBR bf;
                wmma::load_matrix_sync(bf, cur + (ks * 8) * 128 + nt * 16, 128);
                wmma::mma_sync(acc[nt], a, bf, acc[nt]);
            }
        }
        __syncthreads();   // (a) chunk kc+1 fully staged, (b) all compute on cur done
    }
    // all MMA reads for this projection completed at the final barrier above
#pragma unroll
    for (int nt = 0; nt < 8; nt++) {
#pragma unroll
        for (int e = 0; e < acc[nt].num_elements; e++) acc[nt].x[e] = to_tf32(acc[nt].x[e]);
        wmma::store_matrix_sync(dst + (warp * 16) * LDM + nt * 16, acc[nt], LDM, wmma::mem_row_major);
    }
}

__global__ void __launch_bounds__(NTHREADS, 1)
mha_fused_kernel(const float* __restrict__ x,
                 const float* __restrict__ Wq, const float* __restrict__ Wk,
                 const float* __restrict__ Wv, const float* __restrict__ Wp,
                 const float* __restrict__ bp, float* __restrict__ out)
{
    extern __shared__ float sm[];
    float* bufX = sm;                  // X, later V
    float* bufQ = sm + 16384;          // Q, later attention output O (per-head overwrite)
    float* bufK = sm + 32768;          // K, later staged Wp
    float* bufS = sm + 49152;          // weight chunk double-buffer / score half-tiles (64 x 132)

    const int b    = blockIdx.x;
    const int tid  = threadIdx.x;
    const int warp = tid >> 5;

    // ---------------- Phase 0: load X (tf32-converted) ----------------
    const float* xb = x + (size_t)b * (T_SEQ * C_DIM);
    for (int i = tid * 4; i < T_SEQ * C_DIM; i += NTHREADS * 4) {
        float4 v = *reinterpret_cast<const float4*>(xb + i);
        bufX[i + 0] = to_tf32(v.x); bufX[i + 1] = to_tf32(v.y);
        bufX[i + 2] = to_tf32(v.z); bufX[i + 3] = to_tf32(v.w);
    }
    // proj_gemm's first __syncthreads() (after staging chunk 0) covers the X-load barrier.

    // ---------------- Phase 1: projections ----------------
    proj_gemm(Wq, bufQ, bufX, bufS, warp, tid);
    proj_gemm(Wk, bufK, bufX, bufS, warp, tid);
    proj_gemm(Wv, bufX, bufX, bufS, warp, tid);   // V overwrites X (per-warp row ownership)
    __syncthreads();

    // ---------------- Phase 2: attention, per head, per t-half ----------------
    const float scale = 0.08838834764831845f;  // C^-0.5 (C = embed dim!)

#pragma unroll 1
    for (int h = 0; h < H_NUM; h++) {
#pragma unroll 1
        for (int half = 0; half < 2; half++) {
            const int r0 = half * 64;

            // S[64,128] = Q[r0:r0+64, 32h:+32] @ K[:, 32h:+32]^T
            {
                const int wr = warp >> 1, wc = warp & 1;   // 4 x 2 warp grid
                FragC sacc[4];
#pragma unroll
                for (int nt = 0; nt < 4; nt++) wmma::fill_fragment(sacc[nt], 0.0f);
#pragma unroll
                for (int ks = 0; ks < 4; ks++) {
                    FragA a;
                    wmma::load_matrix_sync(a, bufQ + (r0 + wr * 16) * LDM + h * 32 + ks * 8, LDM);
#pragma unroll
                    for (int nt = 0; nt < 4; nt++) {
                        FragBC bf;  // K^T: element (d, s) at bufK[s*LDM + 32h + d]
                        wmma::load_matrix_sync(bf, bufK + (wc * 64 + nt * 16) * LDM + h * 32 + ks * 8, LDM);
                        wmma::mma_sync(sacc[nt], a, bf, sacc[nt]);
                    }
                }
#pragma unroll
                for (int nt = 0; nt < 4; nt++)
                    wmma::store_matrix_sync(bufS + (wr * 16) * LDS_S + wc * 64 + nt * 16,
                                            sacc[nt], LDS_S, wmma::mem_row_major);
            }
            __syncthreads();

            // causal softmax: 4 threads per row, 64 rows
            {
                const int r  = tid >> 2;      // local row 0..63
                const int q4 = tid & 3;
                const int t  = r0 + r;        // global query index
                float* row = bufS + r * LDS_S;
                const int nvalid = t + 1;

                float mx = -1e30f;
                for (int s = q4; s < nvalid; s += 4) mx = fmaxf(mx, row[s] * scale);
                mx = fmaxf(mx, __shfl_xor_sync(0xffffffffu, mx, 1, 4));
                mx = fmaxf(mx, __shfl_xor_sync(0xffffffffu, mx, 2, 4));

                float sum = 0.0f;
                for (int s = q4; s < nvalid; s += 4) {
                    float e = __expf(row[s] * scale - mx);
                    row[s] = e;
                    sum += e;
                }
                sum += __shfl_xor_sync(0xffffffffu, sum, 1, 4);
                sum += __shfl_xor_sync(0xffffffffu, sum, 2, 4);
                const float inv = 1.0f / sum;

                for (int s = q4; s < T_SEQ; s += 4) {
                    float p = (s < nvalid) ? row[s] * inv : 0.0f;
                    row[s] = to_tf32(p);
                }
            }
            __syncthreads();

            // O[64,32] = P[64,128] @ V[:, 32h:+32]; overwrite Q_h rows [r0, r0+64)
            {
                const int orr = (warp >> 1) * 16, oc = (warp & 1) * 16;  // 4 x 2 warp grid
                FragC oacc;
                wmma::fill_fragment(oacc, 0.0f);
#pragma unroll
                for (int ks = 0; ks < 16; ks++) {
                    FragA a;
                    wmma::load_matrix_sync(a, bufS + orr * LDS_S + ks * 8, LDS_S);
                    FragBR bf;  // V row-major: (s, d) at bufX[s*LDM + 32h + d]
                    wmma::load_matrix_sync(bf, bufX + (ks * 8) * LDM + h * 32 + oc, LDM);
                    wmma::mma_sync(oacc, a, bf, oacc);
                }
#pragma unroll
                for (int e = 0; e < oacc.num_elements; e++) oacc.x[e] = to_tf32(oacc.x[e]);
                wmma::store_matrix_sync(bufQ + (r0 + orr) * LDM + h * 32 + oc,
                                        oacc, LDM, wmma::mem_row_major);
            }
            __syncthreads();
        }
    }

    // ---------------- Phase 3: Y = O @ Wp^T + bp ----------------
    // stage Wp (row-major [c][e]) into bufK (K is dead), tf32-converted
    for (int i = tid * 4; i < C_DIM * C_DIM; i += NTHREADS * 4) {
        float4 v = *reinterpret_cast<const float4*>(Wp + i);
        bufK[i + 0] = to_tf32(v.x); bufK[i + 1] = to_tf32(v.y);
        bufK[i + 2] = to_tf32(v.z); bufK[i + 3] = to_tf32(v.w);
    }
    __syncthreads();
    {
        FragC yacc[8];
#pragma unroll
        for (int nt = 0; nt < 8; nt++) wmma::fill_fragment(yacc[nt], 0.0f);
#pragma unroll
        for (int ks = 0; ks < 16; ks++) {
            FragA a;
            wmma::load_matrix_sync(a, bufQ + (warp * 16) * LDM + ks * 8, LDM);
#pragma unroll
            for (int nt = 0; nt < 8; nt++) {
                FragBC bf;  // Wp^T: element (e, c) at bufK[c*LDM + e]
                wmma::load_matrix_sync(bf, bufK + (nt * 16) * LDM + ks * 8, LDM);
                wmma::mma_sync(yacc[nt], a, bf, yacc[nt]);
            }
        }
        // Y staged to bufX (V is dead), fp32
#pragma unroll
        for (int nt = 0; nt < 8; nt++)
            wmma::store_matrix_sync(bufX + (warp * 16) * LDM + nt * 16,
                                    yacc[nt], LDM, wmma::mem_row_major);
    }
    __syncthreads();

    // bias add + coalesced writeout
    float* ob = out + (size_t)b * (T_SEQ * C_DIM);
    for (int i = tid * 4; i < T_SEQ * C_DIM; i += NTHREADS * 4) {
        const int c = i & (C_DIM - 1);
        float4 v = *reinterpret_cast<const float4*>(bufX + i);
        v.x += bp[c + 0]; v.y += bp[c + 1]; v.z += bp[c + 2]; v.w += bp[c + 3];
        *reinterpret_cast<float4*>(ob + i) = v;
    }
}

}  // namespace

extern "C" void kernel_launch(void* const* d_in, const int* in_sizes, int n_in,
                              void* d_out, int out_size)
{
    const float* x  = (const float*)d_in[0];
    const float* Wq = (const float*)d_in[1];
    const float* Wk = (const float*)d_in[2];
    const float* Wv = (const float*)d_in[3];
    const float* Wp = (const float*)d_in[4];
    const float* bp = (const float*)d_in[5];
    float* out = (float*)d_out;

    cudaFuncSetAttribute(mha_fused_kernel,
                         cudaFuncAttributeMaxDynamicSharedMemorySize, SMEM_BYTES);
    mha_fused_kernel<<<4096, NTHREADS, SMEM_BYTES>>>(x, Wq, Wk, Wv, Wp, bp, out);
}

// round 7
// speedup vs baseline: 1.4626x; 1.4626x over previous
#include <cuda_runtime.h>
#include <mma.h>

using namespace nvcuda;

namespace {

constexpr int T_SEQ = 128;
constexpr int C_DIM = 128;
constexpr int H_NUM = 4;
constexpr int D_HEAD = 32;
constexpr int LD = 132;                 // padded leading dim: 132 % 32 = 4 -> 2-way max conflicts
constexpr int NTHREADS = 256;
constexpr int CHUNK_FLOATS = 16 * LD;   // one staged 16x128 weight chunk (LD-padded)

// smem (floats): bufX(128xLD) | bufQ(128xLD) | bufK(128xLD) | bufS(32xLD scores / 2 weight chunks)
constexpr int BUF_FLOATS = T_SEQ * LD;          // 16896
constexpr int S_FLOATS   = 2 * CHUNK_FLOATS;    // 4224 == 32*LD
constexpr int SMEM_FLOATS = 3 * BUF_FLOATS + S_FLOATS;   // 54912
constexpr int SMEM_BYTES = SMEM_FLOATS * (int)sizeof(float);  // 219648

using FragA  = wmma::fragment<wmma::matrix_a, 16, 16, 8, wmma::precision::tf32, wmma::row_major>;
using FragBR = wmma::fragment<wmma::matrix_b, 16, 16, 8, wmma::precision::tf32, wmma::row_major>;
using FragBC = wmma::fragment<wmma::matrix_b, 16, 16, 8, wmma::precision::tf32, wmma::col_major>;
using FragC  = wmma::fragment<wmma::accumulator, 16, 16, 8, float>;

__device__ __forceinline__ float to_tf32(float v) { return wmma::__float_to_tf32(v); }

// dst[128,128] = src(bufX)[128,128] @ W'[128,128], W'[c][h*32+d] = W[h][c][d].
// Weight k-chunks (16x128, LD-padded) double-buffered through bufW, tf32-converted.
// Warp tile 32 rows x 64 cols (4x2 warp grid): per k-step 2 A + 4 B frags for 8 MMAs.
// Each warp reads ONLY its own 32 rows of src, so dst == src (V overwrite) is safe.
__device__ void proj_gemm(const float* __restrict__ W, float* __restrict__ dst,
                          const float* __restrict__ src, float* __restrict__ bufW,
                          int warp, int tid)
{
    FragC acc[2][4];
#pragma unroll
    for (int at = 0; at < 2; at++)
#pragma unroll
        for (int bt = 0; bt < 4; bt++) wmma::fill_fragment(acc[at][bt], 0.0f);

    const int wr = warp >> 1;            // 0..3: 32-row group
    const int wc = warp & 1;             // 0..1: 64-col group

    const int cc    = tid >> 4;          // chunk row 0..15
    const int n0    = (tid & 15) * 8;    // chunk col 0..120 step 8 (stays inside one head)
    const int head  = n0 >> 5;
    const int inner = n0 & 31;
    const float* srcW = W + head * (C_DIM * D_HEAD) + cc * D_HEAD + inner;

    auto stage = [&](int kc, float* dbuf) {
        const float* s = srcW + kc * 16 * D_HEAD;
        float4 u0 = *reinterpret_cast<const float4*>(s);
        float4 u1 = *reinterpret_cast<const float4*>(s + 4);
        float4 w0 = make_float4(to_tf32(u0.x), to_tf32(u0.y), to_tf32(u0.z), to_tf32(u0.w));
        float4 w1 = make_float4(to_tf32(u1.x), to_tf32(u1.y), to_tf32(u1.z), to_tf32(u1.w));
        float* d = dbuf + cc * LD + n0;                 // LD%4==0, n0%4==0 -> aligned
        *reinterpret_cast<float4*>(d)     = w0;
        *reinterpret_cast<float4*>(d + 4) = w1;
    };

    stage(0, bufW);
    __syncthreads();   // chunk 0 staged; also orders preceding src writes vs. MMA reads

#pragma unroll 1
    for (int kc = 0; kc < 8; kc++) {
        float* cur = bufW + (kc & 1) * CHUNK_FLOATS;
        float* nxt = bufW + ((kc & 1) ^ 1) * CHUNK_FLOATS;
        if (kc < 7) stage(kc + 1, nxt);          // overlap gmem load with MMAs
#pragma unroll
        for (int ks = 0; ks < 2; ks++) {
            FragA a[2];
#pragma unroll
            for (int at = 0; at < 2; at++)
                wmma::load_matrix_sync(a[at], src + (wr * 32 + at * 16) * LD + kc * 16 + ks * 8, LD);
#pragma unroll
            for (int bt = 0; bt < 4; bt++) {
                FragBR bf;
                wmma::load_matrix_sync(bf, cur + (ks * 8) * LD + wc * 64 + bt * 16, LD);
                wmma::mma_sync(acc[0][bt], a[0], bf, acc[0][bt]);
                wmma::mma_sync(acc[1][bt], a[1], bf, acc[1][bt]);
            }
        }
        __syncthreads();   // (a) next chunk staged, (b) cur fully consumed
    }
#pragma unroll
    for (int at = 0; at < 2; at++)
#pragma unroll
        for (int bt = 0; bt < 4; bt++) {
#pragma unroll
            for (int e = 0; e < acc[at][bt].num_elements; e++)
                acc[at][bt].x[e] = to_tf32(acc[at][bt].x[e]);
            wmma::store_matrix_sync(dst + (wr * 32 + at * 16) * LD + wc * 64 + bt * 16,
                                    acc[at][bt], LD, wmma::mem_row_major);
        }
}

__global__ void __launch_bounds__(NTHREADS, 1)
mha_fused_kernel(const float* __restrict__ x,
                 const float* __restrict__ Wq, const float* __restrict__ Wk,
                 const float* __restrict__ Wv, const float* __restrict__ Wp,
                 const float* __restrict__ bp, float* __restrict__ out)
{
    extern __shared__ float sm[];
    float* bufX = sm;                       // X, later V, later Y
    float* bufQ = sm + BUF_FLOATS;          // Q, later attention output O
    float* bufK = sm + 2 * BUF_FLOATS;      // K, later staged Wp
    float* bufS = sm + 3 * BUF_FLOATS;      // weight chunks (phase 1) / 32xLD scores (phase 2)

    const int b    = blockIdx.x;
    const int tid  = threadIdx.x;
    const int warp = tid >> 5;

    // ---------------- Phase 0: load X (tf32-converted, LD-padded) ----------------
    const float* xb = x + (size_t)b * (T_SEQ * C_DIM);
    for (int i = tid * 4; i < T_SEQ * C_DIM; i += NTHREADS * 4) {
        const int row = i >> 7, col = i & 127;
        float4 v = *reinterpret_cast<const float4*>(xb + i);
        float4 w = make_float4(to_tf32(v.x), to_tf32(v.y), to_tf32(v.z), to_tf32(v.w));
        *reinterpret_cast<float4*>(bufX + row * LD + col) = w;
    }
    // proj_gemm's first __syncthreads() covers the X-load barrier.

    // ---------------- Phase 1: projections ----------------
    proj_gemm(Wq, bufQ, bufX, bufS, warp, tid);
    proj_gemm(Wk, bufK, bufX, bufS, warp, tid);
    proj_gemm(Wv, bufX, bufX, bufS, warp, tid);   // V overwrites X (per-warp row ownership)
    __syncthreads();

    // ---------------- Phase 2: attention, per head, per 32-row quarter ----------------
    const float scale = 0.08838834764831845f;  // C^-0.5 (C = embed dim!)

#pragma unroll 1
    for (int h = 0; h < H_NUM; h++) {
#pragma unroll 1
        for (int q = 0; q < 4; q++) {
            const int r0 = q * 32;
            const int ctmax = 2 * (q + 1);      // causal: only col tiles with s < 32(q+1)

            // S[32, 32(q+1)] = Q[r0:+32, 32h:+32] @ K[0:32(q+1), 32h:+32]^T
            {
                const int rt = warp >> 2;       // 0..1 (16-row tile)
                const int c0 = warp & 3;
                FragA a4[4];
#pragma unroll
                for (int ks = 0; ks < 4; ks++)
                    wmma::load_matrix_sync(a4[ks], bufQ + (r0 + rt * 16) * LD + h * 32 + ks * 8, LD);
#pragma unroll 1
                for (int ct = c0; ct < ctmax; ct += 4) {
                    FragC sacc;
                    wmma::fill_fragment(sacc, 0.0f);
#pragma unroll
                    for (int ks = 0; ks < 4; ks++) {
                        FragBC bf;  // K^T: element (d, s) at bufK[s*LD + 32h + d]
                        wmma::load_matrix_sync(bf, bufK + (ct * 16) * LD + h * 32 + ks * 8, LD);
                        wmma::mma_sync(sacc, a4[ks], bf, sacc);
                    }
                    wmma::store_matrix_sync(bufS + (rt * 16) * LD + ct * 16, sacc, LD,
                                            wmma::mem_row_major);
                }
            }
            __syncthreads();

            // causal softmax: 8 threads per row, 32 rows
            {
                const int r  = tid >> 3;        // local row 0..31
                const int q8 = tid & 7;
                const int nvalid = r0 + r + 1;
                const int smax = 32 * (q + 1);  // computed score extent
                float* row = bufS + r * LD;

                float mx = -1e30f;
                for (int s = q8; s < nvalid; s += 8) mx = fmaxf(mx, row[s] * scale);
                mx = fmaxf(mx, __shfl_xor_sync(0xffffffffu, mx, 1, 8));
                mx = fmaxf(mx, __shfl_xor_sync(0xffffffffu, mx, 2, 8));
                mx = fmaxf(mx, __shfl_xor_sync(0xffffffffu, mx, 4, 8));

                float sum = 0.0f;
                for (int s = q8; s < nvalid; s += 8) {
                    float e = __expf(row[s] * scale - mx);
                    row[s] = e;
                    sum += e;
                }
                sum += __shfl_xor_sync(0xffffffffu, sum, 1, 8);
                sum += __shfl_xor_sync(0xffffffffu, sum, 2, 8);
                sum += __shfl_xor_sync(0xffffffffu, sum, 4, 8);
                const float inv = 1.0f / sum;

                for (int s = q8; s < smax; s += 8) {
                    float p = (s < nvalid) ? row[s] * inv : 0.0f;
                    row[s] = to_tf32(p);
                }
            }
            __syncthreads();

            // O[32,32] = P[32, 32(q+1)] @ V[0:32(q+1), 32h:+32]; overwrite Q_h rows [r0,r0+32)
            if (warp < 4) {
                const int rt = warp >> 1, vc = warp & 1;
                const int ksmax = 4 * (q + 1);
                FragC oacc;
                wmma::fill_fragment(oacc, 0.0f);
#pragma unroll 1
                for (int ks = 0; ks < ksmax; ks++) {
                    FragA a;
                    wmma::load_matrix_sync(a, bufS + (rt * 16) * LD + ks * 8, LD);
                    FragBR bf;  // V row-major: (s, d) at bufX[s*LD + 32h + d]
                    wmma::load_matrix_sync(bf, bufX + (ks * 8) * LD + h * 32 + vc * 16, LD);
                    wmma::mma_sync(oacc, a, bf, oacc);
                }
#pragma unroll
                for (int e = 0; e < oacc.num_elements; e++) oacc.x[e] = to_tf32(oacc.x[e]);
                wmma::store_matrix_sync(bufQ + (r0 + rt * 16) * LD + h * 32 + vc * 16,
                                        oacc, LD, wmma::mem_row_major);
            }
            __syncthreads();
        }
    }

    // ---------------- Phase 3: Y = O @ Wp^T + bp ----------------
    // stage Wp (row-major [e][c]) into bufK (K is dead), tf32-converted, LD-padded
    for (int i = tid * 4; i < C_DIM * C_DIM; i += NTHREADS * 4) {
        const int row = i >> 7, col = i & 127;
        float4 v = *reinterpret_cast<const float4*>(Wp + i);
        float4 w = make_float4(to_tf32(v.x), to_tf32(v.y), to_tf32(v.z), to_tf32(v.w));
        *reinterpret_cast<float4*>(bufK + row * LD + col) = w;
    }
    __syncthreads();
    {
        // warp tile 32 x 64, operands fully resident (no staging loop)
        const int wr = warp >> 1, wc = warp & 1;
        FragC yacc[2][4];
#pragma unroll
        for (int at = 0; at < 2; at++)
#pragma unroll
            for (int bt = 0; bt < 4; bt++) wmma::fill_fragment(yacc[at][bt], 0.0f);
#pragma unroll 1
        for (int ks = 0; ks < 16; ks++) {
            FragA a[2];
#pragma unroll
            for (int at = 0; at < 2; at++)
                wmma::load_matrix_sync(a[at], bufQ + (wr * 32 + at * 16) * LD + ks * 8, LD);
#pragma unroll
            for (int bt = 0; bt < 4; bt++) {
                FragBC bf;  // Wp^T: element (c, e) at bufK[e*LD + c]
                wmma::load_matrix_sync(bf, bufK + (wc * 64 + bt * 16) * LD + ks * 8, LD);
                wmma::mma_sync(yacc[0][bt], a[0], bf, yacc[0][bt]);
                wmma::mma_sync(yacc[1][bt], a[1], bf, yacc[1][bt]);
            }
        }
        __syncthreads();   // all reads of bufX (V) done in phase 2; Y overwrites bufX
#pragma unroll
        for (int at = 0; at < 2; at++)
#pragma unroll
            for (int bt = 0; bt < 4; bt++)
                wmma::store_matrix_sync(bufX + (wr * 32 + at * 16) * LD + wc * 64 + bt * 16,
                                        yacc[at][bt], LD, wmma::mem_row_major);
    }
    __syncthreads();

    // bias add + coalesced writeout
    float* ob = out + (size_t)b * (T_SEQ * C_DIM);
    for (int i = tid * 4; i < T_SEQ * C_DIM; i += NTHREADS * 4) {
        const int row = i >> 7, col = i & 127;
        float4 v = *reinterpret_cast<const float4*>(bufX + row * LD + col);
        v.x += bp[col + 0]; v.y += bp[col + 1]; v.z += bp[col + 2]; v.w += bp[col + 3];
        *reinterpret_cast<float4*>(ob + i) = v;
    }
}

}  // namespace

extern "C" void kernel_launch(void* const* d_in, const int* in_sizes, int n_in,
                              void* d_out, int out_size)
{
    const float* x  = (const float*)d_in[0];
    const float* Wq = (const float*)d_in[1];
    const float* Wk = (const float*)d_in[2];
    const float* Wv = (const float*)d_in[3];
    const float* Wp = (const float*)d_in[4];
    const float* bp = (const float*)d_in[5];
    float* out = (float*)d_out;

    cudaFuncSetAttribute(mha_fused_kernel,
                         cudaFuncAttributeMaxDynamicSharedMemorySize, SMEM_BYTES);
    mha_fused_kernel<<<4096, NTHREADS, SMEM_BYTES>>>(x, Wq, Wk, Wv, Wp, bp, out);
}

// round 10
// speedup vs baseline: 1.8341x; 1.2540x over previous
#include <cuda_runtime.h>
#include <mma.h>

using namespace nvcuda;

namespace {

constexpr int T_SEQ = 128;
constexpr int C_DIM = 128;
constexpr int D_HEAD = 32;
constexpr int NTHREADS = 256;

// ---------------- kernel A smem layout (floats) ----------------
constexpr int LDP = 100;   // QKV buffer: 128 x 96 (Q|K|V), padded; 100%32=4, %4=0
constexpr int LDS_ = 132;  // score buffer 32 x 132
constexpr int LDX = 20;    // X chunk 128 x 16, padded
constexpr int LDW = 100;   // W chunk 16 x 96, padded
constexpr int OFF_P = 0;                         // 128*100 = 12800
constexpr int OFF_S = 12800;                     // 32*132  = 4224
constexpr int OFF_X = 17024;                     // 2*128*20 = 5120
constexpr int OFF_W = 22144;                     // 2*16*100 = 3200
constexpr int SMEM_A_FLOATS = 25344;
constexpr int SMEM_A = SMEM_A_FLOATS * 4;        // 101376 B -> 2 CTAs/SM

// ---------------- kernel B smem layout (floats) ----------------
constexpr int LDWP = 132;  // Wp half: 64 x 132
constexpr int LDO  = 20;   // O chunk 128 x 16, padded
constexpr int LDR  = 68;   // result 128 x 64, padded
constexpr int OFF_WP = 0;                        // 64*132 = 8448
constexpr int OFF_O  = 8448;                     // 2*128*20 = 5120
constexpr int OFF_R  = 13568;                    // 128*68 = 8704
constexpr int SMEM_B_FLOATS = 22272;
constexpr int SMEM_B = SMEM_B_FLOATS * 4;        // 89088 B -> 2 CTAs/SM

using FragA  = wmma::fragment<wmma::matrix_a, 16, 16, 8, wmma::precision::tf32, wmma::row_major>;
using FragBR = wmma::fragment<wmma::matrix_b, 16, 16, 8, wmma::precision::tf32, wmma::row_major>;
using FragBC = wmma::fragment<wmma::matrix_b, 16, 16, 8, wmma::precision::tf32, wmma::col_major>;
using FragC  = wmma::fragment<wmma::accumulator, 16, 16, 8, float>;

__device__ __forceinline__ float to_tf32(float v) { return wmma::__float_to_tf32(v); }
__device__ __forceinline__ float4 tf4(float4 v) {
    return make_float4(to_tf32(v.x), to_tf32(v.y), to_tf32(v.z), to_tf32(v.w));
}

// O scratch: [B, T, C] f32, head h occupies cols 32h..32h+31
__device__ float g_O[4096 * 128 * 128];

// ================= Kernel A: fused QKV projection + causal attention (per batch, head) =================
__global__ void __launch_bounds__(NTHREADS, 2)
qkv_attn_kernel(const float* __restrict__ x,
                const float* __restrict__ Wq, const float* __restrict__ Wk,
                const float* __restrict__ Wv)
{
    extern __shared__ float sm[];
    float* bufP = sm + OFF_P;   // Q cols 0-31 | K 32-63 | V 64-95; O_h overwrites Q slice
    float* bufS = sm + OFF_S;
    float* bufX = sm + OFF_X;
    float* bufW = sm + OFF_W;

    const int bid  = blockIdx.x;
    const int b    = bid >> 2;
    const int h    = bid & 3;
    const int tid  = threadIdx.x;
    const int warp = tid >> 5;

    const float* xb = x + (size_t)b * (T_SEQ * C_DIM);

    // ---- stage helpers (tf32-converted) ----
    auto stageX = [&](int kc, float* dst) {   // X[:, 16kc:+16] -> 128 x 16 (LDX)
#pragma unroll
        for (int it = 0; it < 2; it++) {
            const int flat = (tid + it * 256) * 4;          // < 2048
            const int row = flat >> 4, col = flat & 15;
            float4 v = *reinterpret_cast<const float4*>(xb + row * C_DIM + kc * 16 + col);
            *reinterpret_cast<float4*>(dst + row * LDX + col) = tf4(v);
        }
    };
    auto stageW = [&](int kc, float* dst) {   // [Wqh|Wkh|Wvh] rows 16kc:+16 -> 16 x 96 (LDW)
        for (int idx = tid; idx < 384; idx += NTHREADS) {
            const int flat = idx * 4;
            const int row = flat / 96, col = flat % 96;
            const int m = col >> 5;
            const float* Ws = (m == 0 ? Wq : (m == 1 ? Wk : Wv)) + h * (C_DIM * D_HEAD);
            float4 v = *reinterpret_cast<const float4*>(Ws + (kc * 16 + row) * D_HEAD + (col & 31));
            *reinterpret_cast<float4*>(dst + row * LDW + col) = tf4(v);
        }
    };

    // ---------------- Phase 1: fused QKV projection [128 x 96] ----------------
    {
        const int wr = warp >> 1;   // 0..3: 32-row group
        const int wc = warp & 1;    // 0..1: 48-col group
        FragC acc[2][3];
#pragma unroll
        for (int at = 0; at < 2; at++)
#pragma unroll
            for (int bt = 0; bt < 3; bt++) wmma::fill_fragment(acc[at][bt], 0.0f);

        stageX(0, bufX);
        stageW(0, bufW);
        __syncthreads();

#pragma unroll 1
        for (int kc = 0; kc < 8; kc++) {
            const float* xc = bufX + (kc & 1) * (128 * LDX);
            const float* wch = bufW + (kc & 1) * (16 * LDW);
            if (kc < 7) {
                stageX(kc + 1, bufX + ((kc & 1) ^ 1) * (128 * LDX));
                stageW(kc + 1, bufW + ((kc & 1) ^ 1) * (16 * LDW));
            }
#pragma unroll
            for (int ks = 0; ks < 2; ks++) {
                FragA a[2];
#pragma unroll
                for (int at = 0; at < 2; at++)
                    wmma::load_matrix_sync(a[at], xc + (wr * 32 + at * 16) * LDX + ks * 8, LDX);
#pragma unroll
                for (int bt = 0; bt < 3; bt++) {
                    FragBR bf;
                    wmma::load_matrix_sync(bf, wch + (ks * 8) * LDW + wc * 48 + bt * 16, LDW);
                    wmma::mma_sync(acc[0][bt], a[0], bf, acc[0][bt]);
                    wmma::mma_sync(acc[1][bt], a[1], bf, acc[1][bt]);
                }
            }
            __syncthreads();
        }
#pragma unroll
        for (int at = 0; at < 2; at++)
#pragma unroll
            for (int bt = 0; bt < 3; bt++) {
#pragma unroll
                for (int e = 0; e < acc[at][bt].num_elements; e++)
                    acc[at][bt].x[e] = to_tf32(acc[at][bt].x[e]);
                wmma::store_matrix_sync(bufP + (wr * 32 + at * 16) * LDP + wc * 48 + bt * 16,
                                        acc[at][bt], LDP, wmma::mem_row_major);
            }
    }
    __syncthreads();

    // ---------------- Phase 2: causal attention, per 32-row quarter ----------------
    const float scale = 0.08838834764831845f;  // C^-0.5 (C = embed dim!)

#pragma unroll 1
    for (int q = 0; q < 4; q++) {
        const int r0 = q * 32;
        const int ctmax = 2 * (q + 1);          // col tiles with s < 32(q+1)

        // S[32, 32(q+1)] = Q[r0:+32, :] @ K[0:32(q+1), :]^T
        {
            const int rt = warp >> 2;           // 0..1
            const int c0 = warp & 3;
            FragA a4[4];
#pragma unroll
            for (int ks = 0; ks < 4; ks++)
                wmma::load_matrix_sync(a4[ks], bufP + (r0 + rt * 16) * LDP + ks * 8, LDP);
#pragma unroll 1
            for (int ct = c0; ct < ctmax; ct += 4) {
                FragC sacc;
                wmma::fill_fragment(sacc, 0.0f);
#pragma unroll
                for (int ks = 0; ks < 4; ks++) {
                    FragBC bf;  // K^T: element (d, s) at bufP[s*LDP + 32 + d]
                    wmma::load_matrix_sync(bf, bufP + (ct * 16) * LDP + 32 + ks * 8, LDP);
                    wmma::mma_sync(sacc, a4[ks], bf, sacc);
                }
                wmma::store_matrix_sync(bufS + (rt * 16) * LDS_ + ct * 16, sacc, LDS_,
                                        wmma::mem_row_major);
            }
        }
        __syncthreads();

        // causal softmax: 8 threads per row, 32 rows
        {
            const int r  = tid >> 3;
            const int q8 = tid & 7;
            const int nvalid = r0 + r + 1;
            const int smax = 32 * (q + 1);
            float* row = bufS + r * LDS_;

            float mx = -1e30f;
            for (int s = q8; s < nvalid; s += 8) mx = fmaxf(mx, row[s] * scale);
            mx = fmaxf(mx, __shfl_xor_sync(0xffffffffu, mx, 1, 8));
            mx = fmaxf(mx, __shfl_xor_sync(0xffffffffu, mx, 2, 8));
            mx = fmaxf(mx, __shfl_xor_sync(0xffffffffu, mx, 4, 8));

            float sum = 0.0f;
            for (int s = q8; s < nvalid; s += 8) {
                float e = __expf(row[s] * scale - mx);
                row[s] = e;
                sum += e;
            }
            sum += __shfl_xor_sync(0xffffffffu, sum, 1, 8);
            sum += __shfl_xor_sync(0xffffffffu, sum, 2, 8);
            sum += __shfl_xor_sync(0xffffffffu, sum, 4, 8);
            const float inv = 1.0f / sum;

            for (int s = q8; s < smax; s += 8) {
                float p = (s < nvalid) ? row[s] * inv : 0.0f;
                row[s] = to_tf32(p);
            }
        }
        __syncthreads();

        // O[32,32] = P @ V; overwrite Q slice rows [r0, r0+32) (dead after this quarter's S)
        if (warp < 4) {
            const int rt = warp >> 1, vc = warp & 1;
            const int ksmax = 4 * (q + 1);
            FragC oacc;
            wmma::fill_fragment(oacc, 0.0f);
#pragma unroll 1
            for (int ks = 0; ks < ksmax; ks++) {
                FragA a;
                wmma::load_matrix_sync(a, bufS + (rt * 16) * LDS_ + ks * 8, LDS_);
                FragBR bf;  // V: (s, d) at bufP[s*LDP + 64 + d]
                wmma::load_matrix_sync(bf, bufP + (ks * 8) * LDP + 64 + vc * 16, LDP);
                wmma::mma_sync(oacc, a, bf, oacc);
            }
            wmma::store_matrix_sync(bufP + (r0 + rt * 16) * LDP + vc * 16,
                                    oacc, LDP, wmma::mem_row_major);   // f32, no rounding
        }
        __syncthreads();
    }

    // ---------------- write O_h (f32) to scratch ----------------
    float* ob = g_O + ((size_t)b * T_SEQ) * C_DIM + h * D_HEAD;
#pragma unroll
    for (int it = 0; it < 4; it++) {
        const int flat = (tid + it * 256) * 4;          // < 4096 = 128*32
        const int row = flat >> 5, col = flat & 31;
        float4 v = *reinterpret_cast<const float4*>(bufP + row * LDP + col);
        *reinterpret_cast<float4*>(ob + row * C_DIM + col) = v;
    }
}

// ================= Kernel B: out = O @ Wp^T + bp =================
__global__ void __launch_bounds__(NTHREADS, 2)
out_proj_kernel(const float* __restrict__ Wp, const float* __restrict__ bp,
                float* __restrict__ out)
{
    extern __shared__ float sm[];
    float* wpb  = sm + OFF_WP;   // Wp rows e0..e0+64 x 128, tf32
    float* obuf = sm + OFF_O;    // O k-chunks, double-buffered
    float* res  = sm + OFF_R;    // 128 x 64 result

    const int bid = blockIdx.x;
    const int b   = bid >> 1;
    const int e0  = (bid & 1) * 64;
    const int tid = threadIdx.x;
    const int warp = tid >> 5;

    const float* Ob = g_O + (size_t)b * (T_SEQ * C_DIM);

    auto stageO = [&](int kc, float* dst) {   // O[:, 16kc:+16] -> 128 x 16 (LDO)
#pragma unroll
        for (int it = 0; it < 2; it++) {
            const int flat = (tid + it * 256) * 4;
            const int row = flat >> 4, col = flat & 15;
            float4 v = *reinterpret_cast<const float4*>(Ob + row * C_DIM + kc * 16 + col);
            *reinterpret_cast<float4*>(dst + row * LDO + col) = tf4(v);
        }
    };

    // stage Wp half: rows e0..e0+64 x cols 0..128
    for (int idx = tid; idx < 2048; idx += NTHREADS) {
        const int flat = idx * 4;
        const int row = flat >> 7, col = flat & 127;
        float4 v = *reinterpret_cast<const float4*>(Wp + (e0 + row) * C_DIM + col);
        *reinterpret_cast<float4*>(wpb + row * LDWP + col) = tf4(v);
    }
    stageO(0, obuf);
    __syncthreads();

    const int wr = warp >> 1, wc = warp & 1;   // warp tile 32 rows x 32 cols
    FragC acc[2][2];
#pragma unroll
    for (int at = 0; at < 2; at++)
#pragma unroll
        for (int bt = 0; bt < 2; bt++) wmma::fill_fragment(acc[at][bt], 0.0f);

#pragma unroll 1
    for (int kc = 0; kc < 8; kc++) {
        const float* oc = obuf + (kc & 1) * (128 * LDO);
        if (kc < 7) stageO(kc + 1, obuf + ((kc & 1) ^ 1) * (128 * LDO));
#pragma unroll
        for (int ks = 0; ks < 2; ks++) {
            FragA a[2];
#pragma unroll
            for (int at = 0; at < 2; at++)
                wmma::load_matrix_sync(a[at], oc + (wr * 32 + at * 16) * LDO + ks * 8, LDO);
#pragma unroll
            for (int bt = 0; bt < 2; bt++) {
                FragBC bf;  // Wp^T: element (c, e_local) at wpb[e_local*LDWP + c]
                // FIX (R8 bug): wpb holds ALL 128 c-columns, so the k offset is
                // the GLOBAL c = kc*16 + ks*8, not the chunk-local ks*8.
                wmma::load_matrix_sync(bf, wpb + (wc * 32 + bt * 16) * LDWP + kc * 16 + ks * 8, LDWP);
                wmma::mma_sync(acc[0][bt], a[0], bf, acc[0][bt]);
                wmma::mma_sync(acc[1][bt], a[1], bf, acc[1][bt]);
            }
        }
        __syncthreads();
    }
#pragma unroll
    for (int at = 0; at < 2; at++)
#pragma unroll
        for (int bt = 0; bt < 2; bt++)
            wmma::store_matrix_sync(res + (wr * 32 + at * 16) * LDR + wc * 32 + bt * 16,
                                    acc[at][bt], LDR, wmma::mem_row_major);
    __syncthreads();

    // bias + coalesced writeout
    float* outb = out + (size_t)b * (T_SEQ * C_DIM) + e0;
    for (int idx = tid; idx < 2048; idx += NTHREADS) {
        const int flat = idx * 4;
        const int row = flat >> 6, col = flat & 63;
        float4 v  = *reinterpret_cast<const float4*>(res + row * LDR + col);
        float4 bv = *reinterpret_cast<const float4*>(bp + e0 + col);
        v.x += bv.x; v.y += bv.y; v.z += bv.z; v.w += bv.w;
        *reinterpret_cast<float4*>(outb + row * C_DIM + col) = v;
    }
}

}  // namespace

extern "C" void kernel_launch(void* const* d_in, const int* in_sizes, int n_in,
                              void* d_out, int out_size)
{
    const float* x  = (const float*)d_in[0];
    const float* Wq = (const float*)d_in[1];
    const float* Wk = (const float*)d_in[2];
    const float* Wv = (const float*)d_in[3];
    const float* Wp = (const float*)d_in[4];
    const float* bp = (const float*)d_in[5];
    float* out = (float*)d_out;

    cudaFuncSetAttribute(qkv_attn_kernel,
                         cudaFuncAttributeMaxDynamicSharedMemorySize, SMEM_A);
    cudaFuncSetAttribute(out_proj_kernel,
                         cudaFuncAttributeMaxDynamicSharedMemorySize, SMEM_B);

    qkv_attn_kernel<<<4096 * 4, NTHREADS, SMEM_A>>>(x, Wq, Wk, Wv);
    out_proj_kernel<<<4096 * 2, NTHREADS, SMEM_B>>>(Wp, bp, out);
}

// round 12
// speedup vs baseline: 1.9334x; 1.0542x over previous
#include <cuda_runtime.h>
#include <mma.h>

using namespace nvcuda;

namespace {

constexpr int T_SEQ = 128;
constexpr int C_DIM = 128;
constexpr int D_HEAD = 32;
constexpr int NTHREADS = 256;

// ---------------- kernel A smem layout (floats) ----------------
constexpr int LDP = 100;   // QKV buffer: 128 x 96 (Q|K|V), padded
constexpr int LDS_ = 132;  // score buffers 32 x 132 (x2, ping-pong)
constexpr int LDX = 20;    // X chunk 128 x 16, padded
constexpr int LDW = 100;   // W chunk 16 x 96, padded
constexpr int OFF_P = 0;                      // 128*100 = 12800
constexpr int OFF_REGION = 12800;             // staging (phase1) / scores (phase2) union
//   phase 1: bufX = region+0 (2*128*20 = 5120), bufW = region+5120 (2*16*100 = 3200)
//   phase 2: sS0 = region+0 (4224), sS1 = region+4224 (4224)
constexpr int REGION_FLOATS = 8448;           // max(8320, 8448)
constexpr int SMEM_A_FLOATS = OFF_REGION + REGION_FLOATS;   // 21248
constexpr int SMEM_A = SMEM_A_FLOATS * 4;     // 84992 B -> 2 CTAs/SM

// ---------------- kernel B smem layout (floats) ----------------
constexpr int LDWP = 132;  // Wp half: 64 x 132
constexpr int LDO  = 36;   // O chunk 128 x 32, padded (36%32=4, %4=0)
constexpr int LDR  = 68;   // result 128 x 64, padded
constexpr int OFF_WP = 0;                     // 64*132 = 8448
constexpr int OFF_O  = 8448;                  // 2*128*36 = 9216
constexpr int OFF_R  = 17664;                 // 128*68 = 8704
constexpr int SMEM_B_FLOATS = 26368;
constexpr int SMEM_B = SMEM_B_FLOATS * 4;     // 105472 B -> 2 CTAs/SM

using FragA  = wmma::fragment<wmma::matrix_a, 16, 16, 8, wmma::precision::tf32, wmma::row_major>;
using FragBR = wmma::fragment<wmma::matrix_b, 16, 16, 8, wmma::precision::tf32, wmma::row_major>;
using FragBC = wmma::fragment<wmma::matrix_b, 16, 16, 8, wmma::precision::tf32, wmma::col_major>;
using FragC  = wmma::fragment<wmma::accumulator, 16, 16, 8, float>;

__device__ __forceinline__ float to_tf32(float v) { return wmma::__float_to_tf32(v); }
__device__ __forceinline__ float4 tf4(float4 v) {
    return make_float4(to_tf32(v.x), to_tf32(v.y), to_tf32(v.z), to_tf32(v.w));
}

// O scratch: [B, T, C] f32, head h occupies cols 32h..32h+31
__device__ float g_O[4096 * 128 * 128];

// ================= Kernel A: fused QKV projection + causal attention (per batch, head) =================
__global__ void __launch_bounds__(NTHREADS, 2)
qkv_attn_kernel(const float* __restrict__ x,
                const float* __restrict__ Wq, const float* __restrict__ Wk,
                const float* __restrict__ Wv)
{
    extern __shared__ float sm[];
    float* bufP   = sm + OFF_P;        // Q cols 0-31 | K 32-63 | V 64-95; O_h overwrites Q slice
    float* region = sm + OFF_REGION;
    float* bufX = region;              // phase 1 only
    float* bufW = region + 5120;       // phase 1 only
    float* sS0  = region;              // phase 2 ping
    float* sS1  = region + 4224;       // phase 2 pong

    const int bid  = blockIdx.x;
    const int b    = bid >> 2;
    const int h    = bid & 3;
    const int tid  = threadIdx.x;
    const int warp = tid >> 5;

    const float* xb = x + (size_t)b * (T_SEQ * C_DIM);

    auto stageX = [&](int kc, float* dst) {   // X[:, 16kc:+16] -> 128 x 16 (LDX)
#pragma unroll
        for (int it = 0; it < 2; it++) {
            const int flat = (tid + it * 256) * 4;          // < 2048
            const int row = flat >> 4, col = flat & 15;
            float4 v = *reinterpret_cast<const float4*>(xb + row * C_DIM + kc * 16 + col);
            *reinterpret_cast<float4*>(dst + row * LDX + col) = tf4(v);
        }
    };
    auto stageW = [&](int kc, float* dst) {   // [Wqh|Wkh|Wvh] rows 16kc:+16 -> 16 x 96 (LDW)
        for (int idx = tid; idx < 384; idx += NTHREADS) {
            const int flat = idx * 4;
            const int row = flat / 96, col = flat % 96;
            const int m = col >> 5;
            const float* Ws = (m == 0 ? Wq : (m == 1 ? Wk : Wv)) + h * (C_DIM * D_HEAD);
            float4 v = *reinterpret_cast<const float4*>(Ws + (kc * 16 + row) * D_HEAD + (col & 31));
            *reinterpret_cast<float4*>(dst + row * LDW + col) = tf4(v);
        }
    };

    // ---------------- Phase 1: fused QKV projection [128 x 96] ----------------
    {
        const int wr = warp >> 1;   // 32-row group
        const int wc = warp & 1;    // 48-col group
        FragC acc[2][3];
#pragma unroll
        for (int at = 0; at < 2; at++)
#pragma unroll
            for (int bt = 0; bt < 3; bt++) wmma::fill_fragment(acc[at][bt], 0.0f);

        stageX(0, bufX);
        stageW(0, bufW);
        __syncthreads();

#pragma unroll 1
        for (int kc = 0; kc < 8; kc++) {
            const float* xc  = bufX + (kc & 1) * (128 * LDX);
            const float* wch = bufW + (kc & 1) * (16 * LDW);
            if (kc < 7) {
                stageX(kc + 1, bufX + ((kc & 1) ^ 1) * (128 * LDX));
                stageW(kc + 1, bufW + ((kc & 1) ^ 1) * (16 * LDW));
            }
#pragma unroll
            for (int ks = 0; ks < 2; ks++) {
                FragA a[2];
#pragma unroll
                for (int at = 0; at < 2; at++)
                    wmma::load_matrix_sync(a[at], xc + (wr * 32 + at * 16) * LDX + ks * 8, LDX);
#pragma unroll
                for (int bt = 0; bt < 3; bt++) {
                    FragBR bf;
                    wmma::load_matrix_sync(bf, wch + (ks * 8) * LDW + wc * 48 + bt * 16, LDW);
                    wmma::mma_sync(acc[0][bt], a[0], bf, acc[0][bt]);
                    wmma::mma_sync(acc[1][bt], a[1], bf, acc[1][bt]);
                }
            }
            __syncthreads();
        }
#pragma unroll
        for (int at = 0; at < 2; at++)
#pragma unroll
            for (int bt = 0; bt < 3; bt++) {
#pragma unroll
                for (int e = 0; e < acc[at][bt].num_elements; e++)
                    acc[at][bt].x[e] = to_tf32(acc[at][bt].x[e]);
                wmma::store_matrix_sync(bufP + (wr * 32 + at * 16) * LDP + wc * 48 + bt * 16,
                                        acc[at][bt], LDP, wmma::mem_row_major);
            }
    }
    __syncthreads();   // bufP complete; staging region now dead -> becomes score buffers

    // ---------------- Phase 2: causal attention, software-pipelined quarters ----------------
    const float scale = 0.08838834764831845f;  // C^-0.5 (C = embed dim!)

    // S(qq): score tile GEMM into dst. wide=true: 8 warps (wl=warp), else 4 warps (wl=warp-4).
    auto s_gemm = [&](int qq, float* dst, int wl, bool wide) {
        const int r0 = qq * 32;
        const int ctmax = 2 * (qq + 1);
        const int rt = wide ? (wl >> 2) : (wl >> 1);
        const int c0 = wide ? (wl & 3) : (wl & 1);
        const int cs = wide ? 4 : 2;
        FragA a4[4];
#pragma unroll
        for (int ks = 0; ks < 4; ks++)
            wmma::load_matrix_sync(a4[ks], bufP + (r0 + rt * 16) * LDP + ks * 8, LDP);
#pragma unroll 1
        for (int ct = c0; ct < ctmax; ct += cs) {
            FragC sacc;
            wmma::fill_fragment(sacc, 0.0f);
#pragma unroll
            for (int ks = 0; ks < 4; ks++) {
                FragBC bf;  // K^T: (d, s) at bufP[s*LDP + 32 + d]
                wmma::load_matrix_sync(bf, bufP + (ct * 16) * LDP + 32 + ks * 8, LDP);
                wmma::mma_sync(sacc, a4[ks], bf, sacc);
            }
            wmma::store_matrix_sync(dst + (rt * 16) * LDS_ + ct * 16, sacc, LDS_,
                                    wmma::mem_row_major);
        }
    };

    // PV(qq): O[32,32] = P @ V, warps 0..3, overwrites Q-slice rows of quarter qq
    auto pv = [&](int qq, const float* S) {
        const int r0 = qq * 32;
        const int rt = warp >> 1, vc = warp & 1;
        const int ksmax = 4 * (qq + 1);
        FragC oacc;
        wmma::fill_fragment(oacc, 0.0f);
#pragma unroll 1
        for (int ks = 0; ks < ksmax; ks++) {
            FragA a;
            wmma::load_matrix_sync(a, S + (rt * 16) * LDS_ + ks * 8, LDS_);
            FragBR bf;  // V: (s, d) at bufP[s*LDP + 64 + d]
            wmma::load_matrix_sync(bf, bufP + (ks * 8) * LDP + 64 + vc * 16, LDP);
            wmma::mma_sync(oacc, a, bf, oacc);
        }
        wmma::store_matrix_sync(bufP + (r0 + rt * 16) * LDP + vc * 16,
                                oacc, LDP, wmma::mem_row_major);   // f32
    };

    s_gemm(0, sS0, warp, true);
    __syncthreads();

#pragma unroll 1
    for (int q = 0; q < 4; q++) {
        float* Scur = (q & 1) ? sS1 : sS0;

        // causal softmax on Scur: 8 threads per row, 32 rows
        {
            const int r  = tid >> 3;
            const int q8 = tid & 7;
            const int nvalid = q * 32 + r + 1;
            const int smax = 32 * (q + 1);
            float* row = Scur + r * LDS_;

            float mx = -1e30f;
            for (int s = q8; s < nvalid; s += 8) mx = fmaxf(mx, row[s] * scale);
            mx = fmaxf(mx, __shfl_xor_sync(0xffffffffu, mx, 1, 8));
            mx = fmaxf(mx, __shfl_xor_sync(0xffffffffu, mx, 2, 8));
            mx = fmaxf(mx, __shfl_xor_sync(0xffffffffu, mx, 4, 8));

            float sum = 0.0f;
            for (int s = q8; s < nvalid; s += 8) {
                float e = __expf(row[s] * scale - mx);
                row[s] = e;
                sum += e;
            }
            sum += __shfl_xor_sync(0xffffffffu, sum, 1, 8);
            sum += __shfl_xor_sync(0xffffffffu, sum, 2, 8);
            sum += __shfl_xor_sync(0xffffffffu, sum, 4, 8);
            const float inv = 1.0f / sum;

            for (int s = q8; s < smax; s += 8) {
                float p = (s < nvalid) ? row[s] * inv : 0.0f;
                row[s] = to_tf32(p);
            }
        }
        __syncthreads();

        // parallel step: PV(q) on warps 0-3 || S(q+1) on warps 4-7 (no barriers inside)
        if (warp < 4)      pv(q, Scur);
        else if (q < 3)    s_gemm(q + 1, (q & 1) ? sS0 : sS1, warp - 4, false);
        __syncthreads();
    }

    // ---------------- write O_h (f32) to scratch ----------------
    float* ob = g_O + ((size_t)b * T_SEQ) * C_DIM + h * D_HEAD;
#pragma unroll
    for (int it = 0; it < 4; it++) {
        const int flat = (tid + it * 256) * 4;          // < 4096 = 128*32
        const int row = flat >> 5, col = flat & 31;
        float4 v = *reinterpret_cast<const float4*>(bufP + row * LDP + col);
        *reinterpret_cast<float4*>(ob + row * C_DIM + col) = v;
    }
}

// ================= Kernel B: out = O @ Wp^T + bp =================
__global__ void __launch_bounds__(NTHREADS, 2)
out_proj_kernel(const float* __restrict__ Wp, const float* __restrict__ bp,
                float* __restrict__ out)
{
    extern __shared__ float sm[];
    float* wpb  = sm + OFF_WP;   // Wp rows e0..e0+64 x 128, tf32
    float* obuf = sm + OFF_O;    // O 32-wide k-chunks, double-buffered
    float* res  = sm + OFF_R;    // 128 x 64 result

    const int bid = blockIdx.x;
    const int b   = bid >> 1;
    const int e0  = (bid & 1) * 64;
    const int tid = threadIdx.x;
    const int warp = tid >> 5;

    const float* Ob = g_O + (size_t)b * (T_SEQ * C_DIM);

    auto stageO = [&](int kc, float* dst) {   // O[:, 32kc:+32] -> 128 x 32 (LDO)
#pragma unroll
        for (int it = 0; it < 4; it++) {
            const int flat = (tid + it * 256) * 4;          // < 4096
            const int row = flat >> 5, col = flat & 31;
            float4 v = *reinterpret_cast<const float4*>(Ob + row * C_DIM + kc * 32 + col);
            *reinterpret_cast<float4*>(dst + row * LDO + col) = tf4(v);
        }
    };

    // stage Wp half: rows e0..e0+64 x cols 0..128
    for (int idx = tid; idx < 2048; idx += NTHREADS) {
        const int flat = idx * 4;
        const int row = flat >> 7, col = flat & 127;
        float4 v = *reinterpret_cast<const float4*>(Wp + (e0 + row) * C_DIM + col);
        *reinterpret_cast<float4*>(wpb + row * LDWP + col) = tf4(v);
    }
    stageO(0, obuf);
    __syncthreads();

    const int wr = warp >> 1, wc = warp & 1;   // warp tile 32 rows x 32 cols
    FragC acc[2][2];
#pragma unroll
    for (int at = 0; at < 2; at++)
#pragma unroll
        for (int bt = 0; bt < 2; bt++) wmma::fill_fragment(acc[at][bt], 0.0f);

#pragma unroll 1
    for (int kc = 0; kc < 4; kc++) {
        const float* oc = obuf + (kc & 1) * (128 * LDO);
        if (kc < 3) stageO(kc + 1, obuf + ((kc & 1) ^ 1) * (128 * LDO));
#pragma unroll
        for (int ks = 0; ks < 4; ks++) {
            FragA a[2];
#pragma unroll
            for (int at = 0; at < 2; at++)
                wmma::load_matrix_sync(a[at], oc + (wr * 32 + at * 16) * LDO + ks * 8, LDO);
#pragma unroll
            for (int bt = 0; bt < 2; bt++) {
                FragBC bf;  // Wp^T: (c, e_local) at wpb[e_local*LDWP + c]; GLOBAL c offset
                wmma::load_matrix_sync(bf, wpb + (wc * 32 + bt * 16) * LDWP + kc * 32 + ks * 8, LDWP);
                wmma::mma_sync(acc[0][bt], a[0], bf, acc[0][bt]);
                wmma::mma_sync(acc[1][bt], a[1], bf, acc[1][bt]);
            }
        }
        __syncthreads();
    }
#pragma unroll
    for (int at = 0; at < 2; at++)
#pragma unroll
        for (int bt = 0; bt < 2; bt++)
            wmma::store_matrix_sync(res + (wr * 32 + at * 16) * LDR + wc * 32 + bt * 16,
                                    acc[at][bt], LDR, wmma::mem_row_major);
    __syncthreads();

    // bias + coalesced writeout
    float* outb = out + (size_t)b * (T_SEQ * C_DIM) + e0;
    for (int idx = tid; idx < 2048; idx += NTHREADS) {
        const int flat = idx * 4;
        const int row = flat >> 6, col = flat & 63;
        float4 v  = *reinterpret_cast<const float4*>(res + row * LDR + col);
        float4 bv = *reinterpret_cast<const float4*>(bp + e0 + col);
        v.x += bv.x; v.y += bv.y; v.z += bv.z; v.w += bv.w;
        *reinterpret_cast<float4*>(outb + row * C_DIM + col) = v;
    }
}

}  // namespace

extern "C" void kernel_launch(void* const* d_in, const int* in_sizes, int n_in,
                              void* d_out, int out_size)
{
    const float* x  = (const float*)d_in[0];
    const float* Wq = (const float*)d_in[1];
    const float* Wk = (const float*)d_in[2];
    const float* Wv = (const float*)d_in[3];
    const float* Wp = (const float*)d_in[4];
    const float* bp = (const float*)d_in[5];
    float* out = (float*)d_out;

    cudaFuncSetAttribute(qkv_attn_kernel,
                         cudaFuncAttributeMaxDynamicSharedMemorySize, SMEM_A);
    cudaFuncSetAttribute(out_proj_kernel,
                         cudaFuncAttributeMaxDynamicSharedMemorySize, SMEM_B);

    qkv_attn_kernel<<<4096 * 4, NTHREADS, SMEM_A>>>(x, Wq, Wk, Wv);
    out_proj_kernel<<<4096 * 2, NTHREADS, SMEM_B>>>(Wp, bp, out);
}